// round 7
// baseline (speedup 1.0000x reference)
#include <cuda_runtime.h>
#include <cuda_fp16.h>
#include <cuda_bf16.h>

// Problem constants
#define BB 64
#define TT 512
#define EE 768
#define HH 128      // hidden per direction
#define KK 11

// ---------------------------------------------------------------------------
// Scratch (device globals; no dynamic allocation allowed)
// ---------------------------------------------------------------------------
__device__ float  g_XP[(size_t)TT * BB * 1024];   // gate x-contributions (fp32)
__device__ __half g_H0h[(size_t)TT * BB * 256];   // layer0 h (fp16, gemm1 A)
__device__ __half g_H1h[(size_t)TT * BB * 256];   // layer1 h (fp16, emis input)
__device__ float  g_EM[(size_t)TT * BB * 16];     // emissions padded to 16
__device__ float  g_ND[BB];                       // num - den per batch

__device__ __forceinline__ float tanha(float x) {
    float r; asm("tanh.approx.f32 %0, %1;" : "=f"(r) : "f"(x)); return r;
}
__device__ __forceinline__ float sigt(float x) {   // sigmoid via tanh
    return fmaf(0.5f, tanha(0.5f * x), 0.5f);
}
__device__ __forceinline__ __half2 u2h2(unsigned int u) {
    __half2 r; *reinterpret_cast<unsigned int*>(&r) = u; return r;
}
__device__ __forceinline__ unsigned h2u(__half2 h) {
    return *reinterpret_cast<unsigned*>(&h);
}
__device__ __forceinline__ void mma_f16(float* d, const unsigned* a, const unsigned* b) {
    asm volatile(
        "mma.sync.aligned.m16n8k16.row.col.f32.f16.f16.f32 "
        "{%0,%1,%2,%3},{%4,%5,%6,%7},{%8,%9},{%0,%1,%2,%3};"
        : "+f"(d[0]), "+f"(d[1]), "+f"(d[2]), "+f"(d[3])
        : "r"(a[0]), "r"(a[1]), "r"(a[2]), "r"(a[3]), "r"(b[0]), "r"(b[1]));
}

// ---------------------------------------------------------------------------
// fp16 tensor-core GEMM (fp32 accum): XP[r][n] = A[r][:].W[n][:] + bias[n]
//   r = t*64+b;  AMODE 0: A=embeds (B,T,E) fp32, row r -> ((r&63)*512+(r>>6))*768
//                AMODE 1: A=g_H0h (row-major 256, fp16)
//   n<512 -> W0/bias0 (fwd), else W1/bias1 (rev)
// Tile BM=128, BN=128, BK=16; 8 warps (2m x 4n), warp tile 64x32.
// SMEM: half2 k2-major [k2][m], stride 136 (conflict-free frags), double buffer.
// ---------------------------------------------------------------------------
#define GBK 16
#define HSTR 136

template<int AMODE>
__global__ __launch_bounds__(256) void gemm_tc(
    const float* __restrict__ Aext, int Kdim,
    const float* __restrict__ W0, const float* __restrict__ W1,
    const float* __restrict__ bi0, const float* __restrict__ bh0,
    const float* __restrict__ bi1, const float* __restrict__ bh1)
{
    __shared__ unsigned As2[2][8 * HSTR];
    __shared__ unsigned Bs2[2][8 * HSTR];
    __shared__ float bias[128];

    const int tid  = threadIdx.x;
    const int lane = tid & 31, wid = tid >> 5;
    const int wm = wid >> 2, wn = wid & 3;        // 2 x 4 warp grid
    const int g = lane >> 2, tig = lane & 3;
    const int row0 = blockIdx.y * 128;
    const int col0 = blockIdx.x * 128;

    if (tid < 128) {
        int n = col0 + tid;
        bias[tid] = (n < 512) ? (bi0[n] + bh0[n]) : (bi1[n - 512] + bh1[n - 512]);
    }

    // global load mapping: per thread 8 values of A, 8 of B per 16-k tile
    const int arow = tid >> 1;             // 0..127
    const int ak   = (tid & 1) * 8;        // 0 or 8
    const int ak2  = ak >> 1;              // 0 or 4
    size_t aoff;
    {
        int r = row0 + arow;
        aoff = (AMODE == 0) ? ((size_t)(r & 63) * 512 + (size_t)(r >> 6)) * 768
                            : (size_t)r * 256;
    }
    const float* Af = Aext;
    const __half* Ah = g_H0h;
    const int nG = col0 + arow;
    const float* wrow = (nG < 512) ? (W0 + (size_t)nG * Kdim)
                                   : (W1 + (size_t)(nG - 512) * Kdim);

    float c[4][4][4];
#pragma unroll
    for (int i = 0; i < 4; i++)
#pragma unroll
        for (int j = 0; j < 4; j++)
#pragma unroll
            for (int q = 0; q < 4; q++) c[i][j][q] = 0.f;

    const int niter = Kdim / GBK;

    float4 av0, av1;     // AMODE 0
    uint4  au0;          // AMODE 1
    float4 bv0, bv1;

    // ---- prologue: tile 0 -> buf 0
    if (AMODE == 0) {
        av0 = *reinterpret_cast<const float4*>(Af + aoff + ak);
        av1 = *reinterpret_cast<const float4*>(Af + aoff + ak + 4);
    } else {
        au0 = *reinterpret_cast<const uint4*>(Ah + aoff + ak);
    }
    bv0 = *reinterpret_cast<const float4*>(wrow + ak);
    bv1 = *reinterpret_cast<const float4*>(wrow + ak + 4);

    if (AMODE == 0) {
        As2[0][(ak2 + 0) * HSTR + arow] = h2u(__floats2half2_rn(av0.x, av0.y));
        As2[0][(ak2 + 1) * HSTR + arow] = h2u(__floats2half2_rn(av0.z, av0.w));
        As2[0][(ak2 + 2) * HSTR + arow] = h2u(__floats2half2_rn(av1.x, av1.y));
        As2[0][(ak2 + 3) * HSTR + arow] = h2u(__floats2half2_rn(av1.z, av1.w));
    } else {
        As2[0][(ak2 + 0) * HSTR + arow] = au0.x;
        As2[0][(ak2 + 1) * HSTR + arow] = au0.y;
        As2[0][(ak2 + 2) * HSTR + arow] = au0.z;
        As2[0][(ak2 + 3) * HSTR + arow] = au0.w;
    }
    Bs2[0][(ak2 + 0) * HSTR + arow] = h2u(__floats2half2_rn(bv0.x, bv0.y));
    Bs2[0][(ak2 + 1) * HSTR + arow] = h2u(__floats2half2_rn(bv0.z, bv0.w));
    Bs2[0][(ak2 + 2) * HSTR + arow] = h2u(__floats2half2_rn(bv1.x, bv1.y));
    Bs2[0][(ak2 + 3) * HSTR + arow] = h2u(__floats2half2_rn(bv1.z, bv1.w));
    __syncthreads();

#pragma unroll 1
    for (int i = 0; i < niter; ++i) {
        const int pb = i & 1;
        if (i + 1 < niter) {
            const int k0 = (i + 1) * GBK;
            if (AMODE == 0) {
                av0 = *reinterpret_cast<const float4*>(Af + aoff + k0 + ak);
                av1 = *reinterpret_cast<const float4*>(Af + aoff + k0 + ak + 4);
            } else {
                au0 = *reinterpret_cast<const uint4*>(Ah + aoff + k0 + ak);
            }
            bv0 = *reinterpret_cast<const float4*>(wrow + k0 + ak);
            bv1 = *reinterpret_cast<const float4*>(wrow + k0 + ak + 4);
        }

        // compute tile i from buf pb
        {
            unsigned af[4][4], bf[4][2];
#pragma unroll
            for (int mt = 0; mt < 4; ++mt) {
                int m0 = wm * 64 + mt * 16;
                af[mt][0] = As2[pb][tig * HSTR + m0 + g];
                af[mt][1] = As2[pb][tig * HSTR + m0 + g + 8];
                af[mt][2] = As2[pb][(tig + 4) * HSTR + m0 + g];
                af[mt][3] = As2[pb][(tig + 4) * HSTR + m0 + g + 8];
            }
#pragma unroll
            for (int nt = 0; nt < 4; ++nt) {
                int n0 = wn * 32 + nt * 8;
                bf[nt][0] = Bs2[pb][tig * HSTR + n0 + g];
                bf[nt][1] = Bs2[pb][(tig + 4) * HSTR + n0 + g];
            }
#pragma unroll
            for (int mt = 0; mt < 4; ++mt)
#pragma unroll
                for (int nt = 0; nt < 4; ++nt)
                    mma_f16(c[mt][nt], af[mt], bf[nt]);
        }

        if (i + 1 < niter) {
            const int nb = pb ^ 1;
            if (AMODE == 0) {
                As2[nb][(ak2 + 0) * HSTR + arow] = h2u(__floats2half2_rn(av0.x, av0.y));
                As2[nb][(ak2 + 1) * HSTR + arow] = h2u(__floats2half2_rn(av0.z, av0.w));
                As2[nb][(ak2 + 2) * HSTR + arow] = h2u(__floats2half2_rn(av1.x, av1.y));
                As2[nb][(ak2 + 3) * HSTR + arow] = h2u(__floats2half2_rn(av1.z, av1.w));
            } else {
                As2[nb][(ak2 + 0) * HSTR + arow] = au0.x;
                As2[nb][(ak2 + 1) * HSTR + arow] = au0.y;
                As2[nb][(ak2 + 2) * HSTR + arow] = au0.z;
                As2[nb][(ak2 + 3) * HSTR + arow] = au0.w;
            }
            Bs2[nb][(ak2 + 0) * HSTR + arow] = h2u(__floats2half2_rn(bv0.x, bv0.y));
            Bs2[nb][(ak2 + 1) * HSTR + arow] = h2u(__floats2half2_rn(bv0.z, bv0.w));
            Bs2[nb][(ak2 + 2) * HSTR + arow] = h2u(__floats2half2_rn(bv1.x, bv1.y));
            Bs2[nb][(ak2 + 3) * HSTR + arow] = h2u(__floats2half2_rn(bv1.z, bv1.w));
        }
        __syncthreads();
    }

    // epilogue: XP(row,col) = c + bias (fp32 — LSTM read path is fp32-fast)
#pragma unroll
    for (int mt = 0; mt < 4; ++mt) {
#pragma unroll
        for (int nt = 0; nt < 4; ++nt) {
            int r  = row0 + wm * 64 + mt * 16 + g;
            int cb = wn * 32 + nt * 8 + 2 * tig;
            int col = col0 + cb;
            float2 v0, v1;
            v0.x = c[mt][nt][0] + bias[cb];
            v0.y = c[mt][nt][1] + bias[cb + 1];
            v1.x = c[mt][nt][2] + bias[cb];
            v1.y = c[mt][nt][3] + bias[cb + 1];
            *reinterpret_cast<float2*>(&g_XP[(size_t)r * 1024 + col]) = v0;
            *reinterpret_cast<float2*>(&g_XP[(size_t)(r + 8) * 1024 + col]) = v1;
        }
    }
}

// ---------------------------------------------------------------------------
// LSTM recurrence: one block per (batch, dir). 512 threads = 16 warps.
// Warp w, lane l: hidden unit u = w*8 + (l&7), gate = l>>3.
// Weights in registers (fp16); h double-buffered in SMEM; tanh.approx
// activations applied pre-shfl; 4 independent half2 chains; pointer marching.
// xp read fp32 (measured-fast path); h written fp16 to g_H0h / g_H1h.
// ---------------------------------------------------------------------------
__global__ __launch_bounds__(512) void lstm_kernel(
    const float* __restrict__ whh_fwd, const float* __restrict__ whh_rev, int layer)
{
    __shared__ uint4 hbuf4[2][16];   // 2 x 128 halves

    const int b   = blockIdx.x >> 1;
    const int dir = blockIdx.x & 1;
    const float* whh = dir ? whh_rev : whh_fwd;

    const int lane = threadIdx.x & 31;
    const int wid  = threadIdx.x >> 5;
    const int u    = wid * 8 + (lane & 7);
    const int gate = lane >> 3;
    const int wrow_idx = gate * 128 + u;

    // weights -> registers (fp16)
    __half2 W[64];
    {
        const float4* wr4 = reinterpret_cast<const float4*>(whh + (size_t)wrow_idx * 128);
#pragma unroll
        for (int i = 0; i < 32; ++i) {
            float4 f = wr4[i];
            W[2 * i]     = __floats2half2_rn(f.x, f.y);
            W[2 * i + 1] = __floats2half2_rn(f.z, f.w);
        }
    }
    if (threadIdx.x < 16) hbuf4[0][threadIdx.x] = make_uint4(0u, 0u, 0u, 0u);
    float cst = 0.f;
    __syncthreads();

    const long xstride = dir ? -(long)(BB * 1024) : (long)(BB * 1024);
    const long hstride = dir ? -(long)(BB * 256)  : (long)(BB * 256);
    const size_t hbase = (size_t)(dir ? (TT - 1) : 0) * (BB * 256)
                       + (size_t)b * 256 + dir * 128 + u;
    const float* xp_p = g_XP + (size_t)(dir ? (TT - 1) : 0) * (BB * 1024)
                             + (size_t)b * 1024 + dir * 512 + wrow_idx;
    __half* hout_p = (layer ? g_H1h : g_H0h) + hbase;

    float xp = __ldg(xp_p);

    for (int t = 0; t < TT; ++t) {
        // prefetch next step's xp (clamped pointer on last step)
        const float* pf = xp_p + ((t < TT - 1) ? xstride : 0);
        float xpn = __ldg(pf);

        const uint4* hb = hbuf4[t & 1];
        __half2 s0 = __floats2half2_rn(0.f, 0.f);
        __half2 s1 = s0, s2 = s0, s3 = s0;
#pragma unroll
        for (int k = 0; k < 4; ++k) {
            uint4 ha = hb[4 * k];
            uint4 hc = hb[4 * k + 1];
            uint4 hd = hb[4 * k + 2];
            uint4 he = hb[4 * k + 3];
            s0 = __hfma2(W[16 * k + 0],  u2h2(ha.x), s0);
            s1 = __hfma2(W[16 * k + 1],  u2h2(ha.y), s1);
            s2 = __hfma2(W[16 * k + 2],  u2h2(ha.z), s2);
            s3 = __hfma2(W[16 * k + 3],  u2h2(ha.w), s3);
            s0 = __hfma2(W[16 * k + 4],  u2h2(hc.x), s0);
            s1 = __hfma2(W[16 * k + 5],  u2h2(hc.y), s1);
            s2 = __hfma2(W[16 * k + 6],  u2h2(hc.z), s2);
            s3 = __hfma2(W[16 * k + 7],  u2h2(hc.w), s3);
            s0 = __hfma2(W[16 * k + 8],  u2h2(hd.x), s0);
            s1 = __hfma2(W[16 * k + 9],  u2h2(hd.y), s1);
            s2 = __hfma2(W[16 * k + 10], u2h2(hd.z), s2);
            s3 = __hfma2(W[16 * k + 11], u2h2(hd.w), s3);
            s0 = __hfma2(W[16 * k + 12], u2h2(he.x), s0);
            s1 = __hfma2(W[16 * k + 13], u2h2(he.y), s1);
            s2 = __hfma2(W[16 * k + 14], u2h2(he.z), s2);
            s3 = __hfma2(W[16 * k + 15], u2h2(he.w), s3);
        }
        __half2 sh = __hadd2(__hadd2(s0, s1), __hadd2(s2, s3));
        float2 f2 = __half22float2(sh);
        const float gval = f2.x + f2.y + xp;

        // activation by owning lane: tanh for gate 2, sigmoid (via tanh) else
        const float act = (gate == 2) ? tanha(gval) : sigt(gval);

        const int src = lane & 7;
        float iv = __shfl_sync(0xffffffffu, act, src);
        float fv = __shfl_sync(0xffffffffu, act, src + 8);
        float gv = __shfl_sync(0xffffffffu, act, src + 16);
        float ov = __shfl_sync(0xffffffffu, act, src + 24);

        if (lane < 8) {
            float cn = fv * cst + iv * gv;
            cst = cn;
            float hn = ov * tanha(cn);
            __half hcvt = __float2half_rn(hn);
            reinterpret_cast<__half*>(&hbuf4[(t & 1) ^ 1][0])[u] = hcvt;
            *hout_p = hcvt;
        }
        xp = xpn;
        xp_p += xstride;
        hout_p += hstride;
        __syncthreads();
    }
}

// ---------------------------------------------------------------------------
// Emissions: EM[r][n] = H1h[r][:] . linear_w[n][:] + linear_b[n], n padded to 16
// ---------------------------------------------------------------------------
__global__ __launch_bounds__(256) void emis_kernel(
    const float* __restrict__ lw, const float* __restrict__ lb)
{
    const int r = blockIdx.x * 16 + (threadIdx.x >> 4);
    const int n = threadIdx.x & 15;
    float acc = 0.f;
    if (n < KK) {
        const uint4*  h4 = reinterpret_cast<const uint4*>(&g_H1h[(size_t)r * 256]);
        const float4* w4 = reinterpret_cast<const float4*>(lw + (size_t)n * 256);
#pragma unroll 8
        for (int k = 0; k < 32; ++k) {
            uint4 hv = h4[k];
            float4 w0 = w4[2 * k], w1 = w4[2 * k + 1];
            float2 a0 = __half22float2(u2h2(hv.x));
            float2 a1 = __half22float2(u2h2(hv.y));
            float2 a2 = __half22float2(u2h2(hv.z));
            float2 a3 = __half22float2(u2h2(hv.w));
            acc += a0.x * w0.x + a0.y * w0.y + a1.x * w0.z + a1.y * w0.w;
            acc += a2.x * w1.x + a2.y * w1.y + a3.x * w1.z + a3.y * w1.w;
        }
        acc += lb[n];
    }
    g_EM[(size_t)r * 16 + n] = acc;
}

// ---------------------------------------------------------------------------
// CRF: one block per batch.
// ---------------------------------------------------------------------------
__global__ __launch_bounds__(256) void crf_kernel(
    const int* __restrict__ tags, const void* __restrict__ maskraw,
    const float* __restrict__ start_t, const float* __restrict__ end_t,
    const float* __restrict__ trans)
{
    __shared__ float ems[TT * 12];
    __shared__ float redf[256];
    __shared__ int   redi[256];
    __shared__ unsigned char maskb[TT];
    __shared__ float s_num;

    const int b = blockIdx.x;
    const int tid = threadIdx.x;

    {
        const unsigned char* mc = reinterpret_cast<const unsigned char*>(maskraw);
        const bool bytewise = (mc[1] != 0);
        const int* mi = reinterpret_cast<const int*>(maskraw);
        for (int t = tid; t < TT; t += 256) {
            maskb[t] = bytewise ? (mc[(size_t)b * TT + t] != 0)
                                : (mi[(size_t)b * TT + t] != 0);
        }
    }
    for (int base = tid; base < TT * 16; base += 256) {
        int t = base >> 4, j = base & 15;
        if (j < KK) ems[t * 12 + j] = g_EM[((size_t)t * BB + b) * 16 + j];
    }
    __syncthreads();

    float part = 0.f;
    int   cnt  = 0;
    for (int t = tid; t < TT; t += 256) cnt += maskb[t] ? 1 : 0;
    for (int t = 1 + tid; t < TT; t += 256) {
        if (maskb[t]) {
            int tp = tags[(size_t)b * TT + t - 1];
            int tc = tags[(size_t)b * TT + t];
            part += trans[tp * KK + tc] + ems[t * 12 + tc];
        }
    }
    redf[tid] = part; redi[tid] = cnt;
    __syncthreads();
    for (int s = 128; s > 0; s >>= 1) {
        if (tid < s) { redf[tid] += redf[tid + s]; redi[tid] += redi[tid + s]; }
        __syncthreads();
    }
    if (tid == 0) {
        int t0 = tags[(size_t)b * TT];
        int seqEnd = redi[0] - 1;
        s_num = start_t[t0] + ems[t0] + redf[0]
              + end_t[tags[(size_t)b * TT + seqEnd]];
    }
    __syncthreads();

    if (tid < 32) {
        const int lane = tid;
        float tcol[KK];
        if (lane < KK) {
#pragma unroll
            for (int i = 0; i < KK; i++) tcol[i] = trans[i * KK + lane];
        } else {
#pragma unroll
            for (int i = 0; i < KK; i++) tcol[i] = 0.f;
        }
        float score = (lane < KK) ? (start_t[lane] + ems[lane]) : -1e30f;

        for (int t = 1; t < TT; ++t) {
            if (maskb[t]) {
                float vi[KK];
                float m = -1e30f;
#pragma unroll
                for (int i = 0; i < KK; i++) {
                    float si = __shfl_sync(0xffffffffu, score, i);
                    vi[i] = si + tcol[i];
                    m = fmaxf(m, vi[i]);
                }
                float ssum = 0.f;
#pragma unroll
                for (int i = 0; i < KK; i++) ssum += __expf(vi[i] - m);
                float nxt = m + __logf(ssum) + ems[t * 12 + lane];
                if (lane < KK) score = nxt;
            }
        }
        float v = (lane < KK) ? (score + end_t[lane]) : -1e30f;
        float m = v;
#pragma unroll
        for (int off = 16; off > 0; off >>= 1)
            m = fmaxf(m, __shfl_xor_sync(0xffffffffu, m, off));
        float e = __expf(v - m);
#pragma unroll
        for (int off = 16; off > 0; off >>= 1)
            e += __shfl_xor_sync(0xffffffffu, e, off);
        float den = m + __logf(e);
        if (lane == 0) g_ND[b] = s_num - den;
    }
}

__global__ void finish_kernel(float* __restrict__ out, int out_n)
{
    __shared__ float s[64];
    int tid = threadIdx.x;
    s[tid] = g_ND[tid];
    __syncthreads();
    for (int st = 32; st > 0; st >>= 1) {
        if (tid < st) s[tid] += s[tid + st];
        __syncthreads();
    }
    if (tid == 0) out[0] = -s[0] / 64.f;
    if (tid > 0 && tid < out_n) out[tid] = 0.f;
}

// ---------------------------------------------------------------------------
extern "C" void kernel_launch(void* const* d_in, const int* in_sizes, int n_in,
                              void* d_out, int out_size)
{
    const float* embeds    = (const float*)d_in[0];
    const int*   tags      = (const int*)d_in[1];
    const void*  mask      = d_in[2];
    const float* w_ih_l0   = (const float*)d_in[3];
    const float* w_hh_l0   = (const float*)d_in[4];
    const float* b_ih_l0   = (const float*)d_in[5];
    const float* b_hh_l0   = (const float*)d_in[6];
    const float* w_ih_l0r  = (const float*)d_in[7];
    const float* w_hh_l0r  = (const float*)d_in[8];
    const float* b_ih_l0r  = (const float*)d_in[9];
    const float* b_hh_l0r  = (const float*)d_in[10];
    const float* w_ih_l1   = (const float*)d_in[11];
    const float* w_hh_l1   = (const float*)d_in[12];
    const float* b_ih_l1   = (const float*)d_in[13];
    const float* b_hh_l1   = (const float*)d_in[14];
    const float* w_ih_l1r  = (const float*)d_in[15];
    const float* w_hh_l1r  = (const float*)d_in[16];
    const float* b_ih_l1r  = (const float*)d_in[17];
    const float* b_hh_l1r  = (const float*)d_in[18];
    const float* linear_w  = (const float*)d_in[19];
    const float* linear_b  = (const float*)d_in[20];
    const float* start_tr  = (const float*)d_in[21];
    const float* end_tr    = (const float*)d_in[22];
    const float* trans     = (const float*)d_in[23];
    (void)in_sizes; (void)n_in;

    dim3 ggrid(8, 256);   // N/128 x M/128

    // layer 0
    gemm_tc<0><<<ggrid, 256>>>(embeds, 768,
                               w_ih_l0, w_ih_l0r, b_ih_l0, b_hh_l0, b_ih_l0r, b_hh_l0r);
    lstm_kernel<<<128, 512>>>(w_hh_l0, w_hh_l0r, 0);

    // layer 1 (A = g_H0h, fp16)
    gemm_tc<1><<<ggrid, 256>>>(nullptr, 256,
                               w_ih_l1, w_ih_l1r, b_ih_l1, b_hh_l1, b_ih_l1r, b_hh_l1r);
    lstm_kernel<<<128, 512>>>(w_hh_l1, w_hh_l1r, 1);

    // emissions + CRF
    emis_kernel<<<2048, 256>>>(linear_w, linear_b);
    crf_kernel<<<64, 256>>>(tags, mask, start_tr, end_tr, trans);
    finish_kernel<<<1, 64>>>((float*)d_out, out_size);
}